// round 11
// baseline (speedup 1.0000x reference)
#include <cuda_runtime.h>
#include <math.h>
#include <float.h>

#define BB 64
#define QQ 900
#define TT 128
#define C1 14    // NUM_CLASSES+1
#define QP 912   // padded Q stride for the transposed prob table (16B aligned)

// Scratch (static device globals; no allocation)
__device__ __align__(16) float g_probT[(size_t)BB*C1*QP];  // -softmax, [b][c][q]
__device__ float  g_lse[BB*QQ];
__device__ double g_basepart[BB*4];          // per-softmax-block sum of nll13
__device__ float  g_partial[BB];
__device__ unsigned g_count = 0;

// ---------------------------------------------------------------------------
// Kernel 0: softmax -> transposed negative-prob table + logsumexp + nll13 sum
// grid (4, B) x 256
// ---------------------------------------------------------------------------
__global__ void __launch_bounds__(256) softmax_kernel(const float* __restrict__ pc)
{
    int b   = blockIdx.y;
    int tid = threadIdx.x;
    int q   = blockIdx.x * 256 + tid;
    int lane = tid & 31, wid = tid >> 5;

    double base = 0.0;
    if (q < QQ) {
        const float* lg = pc + ((size_t)b * QQ + q) * C1;
        float l[C1];
        float m = -FLT_MAX;
        #pragma unroll
        for (int c = 0; c < C1; c++) { l[c] = lg[c]; m = fmaxf(m, l[c]); }
        float logit13 = l[13];
        float s = 0.f;
        #pragma unroll
        for (int c = 0; c < C1; c++) { l[c] = expf(l[c] - m); s += l[c]; }
        float inv = -1.0f / s;                       // negative probs
        float* dst = g_probT + (size_t)b * C1 * QP + q;
        #pragma unroll
        for (int c = 0; c < C1; c++) dst[(size_t)c * QP] = l[c] * inv;
        float lse = m + logf(s);
        g_lse[b * QQ + q] = lse;
        base = (double)(lse - logit13);              // nll at class 13
    }

    __shared__ double red[8];
    #pragma unroll
    for (int o = 16; o; o >>= 1) base += __shfl_down_sync(0xffffffffu, base, o);
    if (lane == 0) red[wid] = base;
    __syncthreads();
    if (tid == 0) {
        double s = 0.0;
        #pragma unroll
        for (int k = 0; k < 8; k++) s += red[k];
        g_basepart[b * 4 + blockIdx.x] = s;
    }
}

// ---------------------------------------------------------------------------
// on-the-fly cost of (target t, query j):  L1(boxes) + (-prob[label_t][j])
// ---------------------------------------------------------------------------
__device__ __forceinline__ float cost_el(float4 pq, float4 t4, float cc)
{
    return (fabsf(pq.x - t4.x) + fabsf(pq.y - t4.y)) +
           (fabsf(pq.z - t4.z) + fabsf(pq.w - t4.w)) + cc;
}

// ---------------------------------------------------------------------------
// Kernel 1: fused cost + exact assignment (JV successive shortest paths with
// row-reduction init) + per-batch losses + last-block finalize.
// One 256-thread block per batch; costs are never materialized.
// ---------------------------------------------------------------------------
__global__ void __launch_bounds__(256) hungarian_kernel(
    const float* __restrict__ pc, const float* __restrict__ pb,
    const int* __restrict__ tl, const float* __restrict__ tb,
    float* __restrict__ outp)
{
    int b = blockIdx.x;
    int tid = threadIdx.x;
    int lane = tid & 31, wid = tid >> 5;

    __shared__ float  v[QQ + 1];
    __shared__ float  spc[QQ + 1];
    __shared__ float  u[TT + 1];
    __shared__ short  p[QQ + 1];
    __shared__ short  way[QQ + 1];
    __shared__ unsigned char used[QQ + 1];
    __shared__ int    claim[QQ + 1];
    __shared__ short  tree[QQ + 1];
    __shared__ short  rowargmin[TT];
    __shared__ short  freerows[TT];
    __shared__ short  predq[TT];
    __shared__ float4 spb[QQ];          // predicted boxes
    __shared__ float4 stb[TT];          // target boxes
    __shared__ int    slab[TT];         // target labels
    __shared__ float  pm_v[TT][8];      // phase-1 per-stripe partial min
    __shared__ short  pm_j[TT][8];
    __shared__ int    s_nfree, s_ntree, s_j1, s_i0, s_done, s_last;
    __shared__ float  s_minval, s_ui0;
    __shared__ float  red_v[8];
    __shared__ int    red_j[8];
    __shared__ double redd[8][3];
    __shared__ double sw[2];

    const float* probB = g_probT + (size_t)b * C1 * QP;

    for (int j = tid; j <= QQ; j += 256) { v[j] = 0.0f; p[j] = 0; claim[j] = 0x7fffffff; }
    for (int k = tid; k < QQ; k += 256) spb[k] = ((const float4*)pb)[b * QQ + k];
    if (tid < TT) {
        stb[tid]  = ((const float4*)tb)[b * TT + tid];
        slab[tid] = tl[b * TT + tid];
    }
    if (tid == 0) s_nfree = 0;
    __syncthreads();

    // ---- phase 1: fused cost + row minima. Warp w owns columns
    // [116w, 116w+116) (stripe 7: 88 cols); lane holds 4 boxes in registers.
    {
        int start = wid * 116;
        int j0    = start + lane * 4;                     // 4 contiguous columns
        int lim   = (wid == 7) ? 900 : (start + 116);
        bool ok   = (j0 < lim);                            // full quad or none
        float4 pq0, pq1, pq2, pq3;
        if (ok) { pq0 = spb[j0]; pq1 = spb[j0+1]; pq2 = spb[j0+2]; pq3 = spb[j0+3]; }

        for (int t = 0; t < TT; t++) {
            float4 t4 = stb[t];
            const float* prow = probB + (size_t)slab[t] * QP;
            float bv = FLT_MAX;
            int   bj = 0x7fffffff;
            if (ok) {
                const float4 cc = *(const float4*)(prow + j0);
                float c0 = cost_el(pq0, t4, cc.x);
                float c1 = cost_el(pq1, t4, cc.y);
                float c2 = cost_el(pq2, t4, cc.z);
                float c3 = cost_el(pq3, t4, cc.w);
                bv = c0; bj = j0;
                if (c1 < bv) { bv = c1; bj = j0 + 1; }
                if (c2 < bv) { bv = c2; bj = j0 + 2; }
                if (c3 < bv) { bv = c3; bj = j0 + 3; }
            }
            #pragma unroll
            for (int o = 16; o; o >>= 1) {
                float ov = __shfl_down_sync(0xffffffffu, bv, o);
                int   oj = __shfl_down_sync(0xffffffffu, bj, o);
                if (ov < bv || (ov == bv && oj < bj)) { bv = ov; bj = oj; }
            }
            if (lane == 0) { pm_v[t][wid] = bv; pm_j[t][wid] = (short)bj; }
        }
    }
    __syncthreads();
    if (tid < TT) {
        float bv = pm_v[tid][0];
        int   bj = pm_j[tid][0];
        #pragma unroll
        for (int k = 1; k < 8; k++) {
            float ov = pm_v[tid][k];
            if (ov < bv) { bv = ov; bj = pm_j[tid][k]; }   // stripes ascend in j
        }
        u[tid + 1] = bv;
        rowargmin[tid] = (short)bj;
    }
    __syncthreads();

    // ---- phase 2: greedy matching on tight argmin edges ----
    if (tid < TT) atomicMin(&claim[rowargmin[tid] + 1], tid);
    __syncthreads();
    if (tid < TT) {
        int j = rowargmin[tid] + 1;
        if (claim[j] == tid) p[j] = (short)(tid + 1);
        else {
            int k = atomicAdd(&s_nfree, 1);
            freerows[k] = (short)(tid + 1);
        }
    }
    __syncthreads();
    int nfree = s_nfree;

    // ---- phase 3: Dijkstra augment for each free row (on-the-fly costs) ----
    for (int fi = 0; fi < nfree; fi++) {
        int i = freerows[fi];
        for (int j = tid; j <= QQ; j += 256) { spc[j] = FLT_MAX; used[j] = 0; }
        if (tid == 0) {
            p[0] = (short)i;
            spc[0] = 0.0f;
            s_minval = 0.0f;
            s_ui0 = u[i];
            s_i0 = i;
            s_j1 = 0;
            s_done = 0;
            used[0] = 1;
            tree[0] = 0;
            s_ntree = 1;
        }
        __syncthreads();

        while (1) {
            int   j1prev = s_j1;
            float base   = s_minval - s_ui0;
            int   i0     = s_i0;
            float4 t4 = stb[i0 - 1];
            const float* prow = probB + (size_t)slab[i0 - 1] * QP;

            float bv = FLT_MAX;
            int   bj = 0x7fffffff;
            for (int j = tid + 1; j <= QQ; j += 256) {
                if (!used[j] && j != j1prev) {
                    float cst = cost_el(spb[j - 1], t4, prow[j - 1]);
                    float r = base + cst - v[j];
                    float m = spc[j];
                    if (r < m) { m = r; spc[j] = r; way[j] = (short)j1prev; }
                    if (m < bv) { bv = m; bj = j; }
                }
            }
            #pragma unroll
            for (int o = 16; o; o >>= 1) {
                float ov = __shfl_down_sync(0xffffffffu, bv, o);
                int   oj = __shfl_down_sync(0xffffffffu, bj, o);
                if (ov < bv || (ov == bv && oj < bj)) { bv = ov; bj = oj; }
            }
            if (lane == 0) { red_v[wid] = bv; red_j[wid] = bj; }
            __syncthreads();
            if (wid == 0) {
                bv = (lane < 8) ? red_v[lane] : FLT_MAX;
                bj = (lane < 8) ? red_j[lane] : 0x7fffffff;
                #pragma unroll
                for (int o = 4; o; o >>= 1) {
                    float ov = __shfl_down_sync(0xffffffffu, bv, o);
                    int   oj = __shfl_down_sync(0xffffffffu, bj, o);
                    if (ov < bv || (ov == bv && oj < bj)) { bv = ov; bj = oj; }
                }
                if (lane == 0) {
                    if (j1prev != 0) {
                        used[j1prev] = 1;
                        tree[s_ntree++] = (short)j1prev;
                    }
                    int r = p[bj];
                    s_minval = bv;
                    s_j1 = bj;
                    if (r == 0) s_done = 1;
                    else { s_i0 = r; s_ui0 = u[r]; }
                }
            }
            __syncthreads();
            if (s_done) break;
        }

        float minF = s_minval;
        int sink = s_j1;
        int ntree = s_ntree;

        for (int k = tid; k < ntree; k += 256) {
            int j = tree[k];
            float d = minF - spc[j];
            u[p[j]] += d;
            v[j]    -= d;
        }
        __syncthreads();

        if (tid == 0) {
            int j0 = sink;
            while (j0) {
                int jn = way[j0];
                p[j0] = p[jn];
                j0 = jn;
            }
        }
        __syncthreads();
    }

    // emit assignment into shared
    for (int j = tid + 1; j <= QQ; j += 256) {
        int r = p[j];
        if (r > 0) predq[r - 1] = (short)(j - 1);
    }
    __syncthreads();

    // ---- fused per-batch losses ----
    double l1sum = 0.0, gsum = 0.0, cls = 0.0;
    if (tid < TT) {
        int t = tid;
        int q = predq[t];
        int lab = slab[t];
        float4 pq = spb[q];
        float4 t4 = stb[t];
        float px = pq.x, py = pq.y, pw = pq.z, ph = pq.w;
        float tx = t4.x, ty = t4.y, tw = t4.z, th = t4.w;

        l1sum = (double)(fabsf(px - tx) + fabsf(py - ty) +
                         fabsf(pw - tw) + fabsf(ph - th));

        float p1x = px - 0.5f * pw, p1y = py - 0.5f * ph;
        float p2x = px + 0.5f * pw, p2y = py + 0.5f * ph;
        float t1x = tx - 0.5f * tw, t1y = ty - 0.5f * th;
        float t2x = tx + 0.5f * tw, t2y = ty + 0.5f * th;
        float a1 = (p2x - p1x) * (p2y - p1y);
        float a2 = (t2x - t1x) * (t2y - t1y);
        float ltx = fmaxf(p1x, t1x), lty = fmaxf(p1y, t1y);
        float rbx = fminf(p2x, t2x), rby = fminf(p2y, t2y);
        float iw = fmaxf(rbx - ltx, 0.f), ih = fmaxf(rby - lty, 0.f);
        float inter = iw * ih;
        float uni = a1 + a2 - inter;
        float iou = inter / uni;
        float cx1 = fminf(p1x, t1x), cy1 = fminf(p1y, t1y);
        float cx2 = fmaxf(p2x, t2x), cy2 = fmaxf(p2y, t2y);
        float ac = (cx2 - cx1) * (cy2 - cy1);
        gsum = (double)(iou - (ac - uni) / ac);

        float lse = g_lse[b * QQ + q];
        const float* pcl = pc + ((size_t)b * QQ + q) * C1;
        float nll_lab = lse - pcl[lab];
        float nll13   = lse - pcl[13];
        cls = (double)nll_lab - 0.05 * (double)nll13;
    }

    #pragma unroll
    for (int o = 16; o; o >>= 1) {
        l1sum += __shfl_down_sync(0xffffffffu, l1sum, o);
        gsum  += __shfl_down_sync(0xffffffffu, gsum, o);
        cls   += __shfl_down_sync(0xffffffffu, cls, o);
    }
    if (lane == 0) { redd[wid][0] = l1sum; redd[wid][1] = gsum; redd[wid][2] = cls; }
    __syncthreads();
    if (tid == 0) {
        double a = 0, g = 0, c = 0;
        #pragma unroll
        for (int k = 0; k < 4; k++) { a += redd[k][0]; g += redd[k][1]; c += redd[k][2]; }
        double base = g_basepart[b*4+0] + g_basepart[b*4+1] +
                      g_basepart[b*4+2] + g_basepart[b*4+3];
        double clsum = 0.05 * base + c;
        double wsum  = 128.0 + 772.0 * 0.05;
        double l1mean = a / (double)(TT * 4);
        double bbox = 5.0 * l1mean + 2.0 * (1.0 - g / (double)TT);
        g_partial[b] = (float)(bbox + clsum / wsum);
        __threadfence();
        unsigned old = atomicAdd(&g_count, 1u);
        s_last = (old == BB - 1) ? 1 : 0;
    }
    __syncthreads();

    if (s_last) {
        __threadfence();   // acquire: all g_partial visible
        double s = (tid < BB) ? (double)g_partial[tid] : 0.0;
        #pragma unroll
        for (int o = 16; o; o >>= 1) s += __shfl_down_sync(0xffffffffu, s, o);
        if (tid < 64 && lane == 0) sw[wid] = s;
        __syncthreads();
        if (tid == 0) {
            outp[0] = (float)((sw[0] + sw[1]) / (double)(BB * TT));
            g_count = 0;   // reset for next graph replay
        }
    }
}

// ---------------------------------------------------------------------------
extern "C" void kernel_launch(void* const* d_in, const int* in_sizes, int n_in,
                              void* d_out, int out_size)
{
    const float* pc = (const float*)d_in[0];  // predicted_class [B,Q,14]
    const float* pb = (const float*)d_in[1];  // predicted_bbox  [B,Q,4]
    const int*   tl = (const int*)d_in[2];    // target_labels   [B,T]
    const float* tb = (const float*)d_in[3];  // target_boxes    [B,T,4]

    softmax_kernel<<<dim3(4, BB), 256>>>(pc);
    hungarian_kernel<<<BB, 256>>>(pc, pb, tl, tb, (float*)d_out);
}

// round 12
// speedup vs baseline: 1.3376x; 1.3376x over previous
#include <cuda_runtime.h>
#include <math.h>
#include <float.h>

#define BB 64
#define QQ 900
#define TT 128
#define C1 14    // NUM_CLASSES+1
#define QP 912   // padded Q stride for the transposed prob table (16B aligned)

// Scratch (static device globals; no allocation)
__device__ __align__(16) float g_probT[(size_t)BB*C1*QP];  // -softmax, [b][c][q]
__device__ float  g_lse[BB*QQ];
__device__ double g_basepart[BB*4];          // per-softmax-block sum of nll13
__device__ float  g_u[BB*TT];                // row minima
__device__ int    g_amin[BB*TT];             // row argmin (0-based col)
__device__ float  g_partial[BB];
__device__ unsigned g_count = 0;

// ---------------------------------------------------------------------------
// Kernel 0: softmax -> transposed negative-prob table + logsumexp + nll13 sum
// grid (4, B) x 256
// ---------------------------------------------------------------------------
__global__ void __launch_bounds__(256) softmax_kernel(const float* __restrict__ pc)
{
    int b   = blockIdx.y;
    int tid = threadIdx.x;
    int q   = blockIdx.x * 256 + tid;
    int lane = tid & 31, wid = tid >> 5;

    double base = 0.0;
    if (q < QQ) {
        const float* lg = pc + ((size_t)b * QQ + q) * C1;
        float l[C1];
        float m = -FLT_MAX;
        #pragma unroll
        for (int c = 0; c < C1; c++) { l[c] = lg[c]; m = fmaxf(m, l[c]); }
        float logit13 = l[13];
        float s = 0.f;
        #pragma unroll
        for (int c = 0; c < C1; c++) { l[c] = expf(l[c] - m); s += l[c]; }
        float inv = -1.0f / s;                       // negative probs
        float* dst = g_probT + (size_t)b * C1 * QP + q;
        #pragma unroll
        for (int c = 0; c < C1; c++) dst[(size_t)c * QP] = l[c] * inv;
        float lse = m + logf(s);
        g_lse[b * QQ + q] = lse;
        base = (double)(lse - logit13);              // nll at class 13
    }

    __shared__ double red[8];
    #pragma unroll
    for (int o = 16; o; o >>= 1) base += __shfl_down_sync(0xffffffffu, base, o);
    if (lane == 0) red[wid] = base;
    __syncthreads();
    if (tid == 0) {
        double s = 0.0;
        #pragma unroll
        for (int k = 0; k < 8; k++) s += red[k];
        g_basepart[b * 4 + blockIdx.x] = s;
    }
}

// ---------------------------------------------------------------------------
// on-the-fly cost of (target t, query j):  L1(boxes) + (-prob[label_t][j])
// Must be byte-identical in rowmin_kernel and hungarian_kernel.
// ---------------------------------------------------------------------------
__device__ __forceinline__ float cost_el(float4 pq, float4 t4, float cc)
{
    return (fabsf(pq.x - t4.x) + fabsf(pq.y - t4.y)) +
           (fabsf(pq.z - t4.z) + fabsf(pq.w - t4.w)) + cc;
}

// ---------------------------------------------------------------------------
// Kernel 1: row minima with on-the-fly costs. One warp per (b,t) row.
// grid (16, B) x 256  (8 warps/block -> 8 rows/block)
// ---------------------------------------------------------------------------
__global__ void __launch_bounds__(256) rowmin_kernel(
    const float* __restrict__ pb, const int* __restrict__ tl,
    const float* __restrict__ tb)
{
    int b    = blockIdx.y;
    int lane = threadIdx.x & 31;
    int t    = blockIdx.x * 8 + (threadIdx.x >> 5);

    const float4 t4 = ((const float4*)tb)[b * TT + t];
    const float* prow = g_probT + ((size_t)b * C1 + tl[b * TT + t]) * QP;
    const float4* pbB = (const float4*)pb + (size_t)b * QQ;

    float bv = FLT_MAX;
    int   bj = 0x7fffffff;
    for (int j = lane; j < QQ; j += 32) {
        float c = cost_el(pbB[j], t4, prow[j]);
        if (c < bv) { bv = c; bj = j; }      // strided scan keeps lowest j per lane
    }
    #pragma unroll
    for (int o = 16; o; o >>= 1) {
        float ov = __shfl_down_sync(0xffffffffu, bv, o);
        int   oj = __shfl_down_sync(0xffffffffu, bj, o);
        if (ov < bv || (ov == bv && oj < bj)) { bv = ov; bj = oj; }
    }
    if (lane == 0) {
        g_u[b * TT + t]    = bv;
        g_amin[b * TT + t] = bj;
    }
}

// ---------------------------------------------------------------------------
// Kernel 2: greedy matching + Dijkstra augments (on-the-fly costs) + fused
// per-batch losses + last-block finalize. One 256-thread block per batch.
// ---------------------------------------------------------------------------
__global__ void __launch_bounds__(256) hungarian_kernel(
    const float* __restrict__ pc, const float* __restrict__ pb,
    const int* __restrict__ tl, const float* __restrict__ tb,
    float* __restrict__ outp)
{
    int b = blockIdx.x;
    int tid = threadIdx.x;
    int lane = tid & 31, wid = tid >> 5;

    __shared__ float  v[QQ + 1];
    __shared__ float  spc[QQ + 1];
    __shared__ float  u[TT + 1];
    __shared__ short  p[QQ + 1];
    __shared__ short  way[QQ + 1];
    __shared__ unsigned char used[QQ + 1];
    __shared__ int    claim[QQ + 1];
    __shared__ short  tree[QQ + 1];
    __shared__ short  freerows[TT];
    __shared__ short  predq[TT];
    __shared__ float4 spb[QQ];          // predicted boxes
    __shared__ float4 stb[TT];          // target boxes
    __shared__ int    slab[TT];         // target labels
    __shared__ int    s_nfree, s_ntree, s_j1, s_i0, s_done, s_last;
    __shared__ float  s_minval, s_ui0;
    __shared__ float  red_v[8];
    __shared__ int    red_j[8];
    __shared__ double redd[8][3];
    __shared__ double sw[2];

    const float* probB = g_probT + (size_t)b * C1 * QP;

    for (int j = tid; j <= QQ; j += 256) { v[j] = 0.0f; p[j] = 0; claim[j] = 0x7fffffff; }
    for (int k = tid; k < QQ; k += 256) spb[k] = ((const float4*)pb)[b * QQ + k];
    if (tid < TT) {
        stb[tid]  = ((const float4*)tb)[b * TT + tid];
        slab[tid] = tl[b * TT + tid];
        u[tid + 1] = g_u[b * TT + tid];
    }
    if (tid == 0) s_nfree = 0;
    __syncthreads();

    // ---- greedy matching on tight argmin edges (winner = lowest row) ----
    int myamin = -1;
    if (tid < TT) {
        myamin = g_amin[b * TT + tid];
        atomicMin(&claim[myamin + 1], tid);
    }
    __syncthreads();
    if (tid < TT) {
        int j = myamin + 1;
        if (claim[j] == tid) p[j] = (short)(tid + 1);
        else {
            int k = atomicAdd(&s_nfree, 1);
            freerows[k] = (short)(tid + 1);
        }
    }
    __syncthreads();
    int nfree = s_nfree;

    // ---- Dijkstra augment for each free row (on-the-fly costs) ----
    for (int fi = 0; fi < nfree; fi++) {
        int i = freerows[fi];
        for (int j = tid; j <= QQ; j += 256) { spc[j] = FLT_MAX; used[j] = 0; }
        if (tid == 0) {
            p[0] = (short)i;
            spc[0] = 0.0f;
            s_minval = 0.0f;
            s_ui0 = u[i];
            s_i0 = i;
            s_j1 = 0;
            s_done = 0;
            used[0] = 1;
            tree[0] = 0;
            s_ntree = 1;
        }
        __syncthreads();

        while (1) {
            int   j1prev = s_j1;
            float base   = s_minval - s_ui0;
            int   i0     = s_i0;
            float4 t4 = stb[i0 - 1];
            const float* prow = probB + (size_t)slab[i0 - 1] * QP;

            float bv = FLT_MAX;
            int   bj = 0x7fffffff;
            for (int j = tid + 1; j <= QQ; j += 256) {
                if (!used[j] && j != j1prev) {
                    float cst = cost_el(spb[j - 1], t4, prow[j - 1]);
                    float r = base + cst - v[j];
                    float m = spc[j];
                    if (r < m) { m = r; spc[j] = r; way[j] = (short)j1prev; }
                    if (m < bv) { bv = m; bj = j; }
                }
            }
            #pragma unroll
            for (int o = 16; o; o >>= 1) {
                float ov = __shfl_down_sync(0xffffffffu, bv, o);
                int   oj = __shfl_down_sync(0xffffffffu, bj, o);
                if (ov < bv || (ov == bv && oj < bj)) { bv = ov; bj = oj; }
            }
            if (lane == 0) { red_v[wid] = bv; red_j[wid] = bj; }
            __syncthreads();
            if (wid == 0) {
                bv = (lane < 8) ? red_v[lane] : FLT_MAX;
                bj = (lane < 8) ? red_j[lane] : 0x7fffffff;
                #pragma unroll
                for (int o = 4; o; o >>= 1) {
                    float ov = __shfl_down_sync(0xffffffffu, bv, o);
                    int   oj = __shfl_down_sync(0xffffffffu, bj, o);
                    if (ov < bv || (ov == bv && oj < bj)) { bv = ov; bj = oj; }
                }
                if (lane == 0) {
                    if (j1prev != 0) {
                        used[j1prev] = 1;
                        tree[s_ntree++] = (short)j1prev;
                    }
                    int r = p[bj];
                    s_minval = bv;
                    s_j1 = bj;
                    if (r == 0) s_done = 1;
                    else { s_i0 = r; s_ui0 = u[r]; }
                }
            }
            __syncthreads();
            if (s_done) break;
        }

        float minF = s_minval;
        int sink = s_j1;
        int ntree = s_ntree;

        for (int k = tid; k < ntree; k += 256) {
            int j = tree[k];
            float d = minF - spc[j];
            u[p[j]] += d;
            v[j]    -= d;
        }
        __syncthreads();

        if (tid == 0) {
            int j0 = sink;
            while (j0) {
                int jn = way[j0];
                p[j0] = p[jn];
                j0 = jn;
            }
        }
        __syncthreads();
    }

    // emit assignment into shared
    for (int j = tid + 1; j <= QQ; j += 256) {
        int r = p[j];
        if (r > 0) predq[r - 1] = (short)(j - 1);
    }
    __syncthreads();

    // ---- fused per-batch losses ----
    double l1sum = 0.0, gsum = 0.0, cls = 0.0;
    if (tid < TT) {
        int t = tid;
        int q = predq[t];
        int lab = slab[t];
        float4 pq = spb[q];
        float4 t4 = stb[t];
        float px = pq.x, py = pq.y, pw = pq.z, ph = pq.w;
        float tx = t4.x, ty = t4.y, tw = t4.z, th = t4.w;

        l1sum = (double)(fabsf(px - tx) + fabsf(py - ty) +
                         fabsf(pw - tw) + fabsf(ph - th));

        float p1x = px - 0.5f * pw, p1y = py - 0.5f * ph;
        float p2x = px + 0.5f * pw, p2y = py + 0.5f * ph;
        float t1x = tx - 0.5f * tw, t1y = ty - 0.5f * th;
        float t2x = tx + 0.5f * tw, t2y = ty + 0.5f * th;
        float a1 = (p2x - p1x) * (p2y - p1y);
        float a2 = (t2x - t1x) * (t2y - t1y);
        float ltx = fmaxf(p1x, t1x), lty = fmaxf(p1y, t1y);
        float rbx = fminf(p2x, t2x), rby = fminf(p2y, t2y);
        float iw = fmaxf(rbx - ltx, 0.f), ih = fmaxf(rby - lty, 0.f);
        float inter = iw * ih;
        float uni = a1 + a2 - inter;
        float iou = inter / uni;
        float cx1 = fminf(p1x, t1x), cy1 = fminf(p1y, t1y);
        float cx2 = fmaxf(p2x, t2x), cy2 = fmaxf(p2y, t2y);
        float ac = (cx2 - cx1) * (cy2 - cy1);
        gsum = (double)(iou - (ac - uni) / ac);

        float lse = g_lse[b * QQ + q];
        const float* pcl = pc + ((size_t)b * QQ + q) * C1;
        float nll_lab = lse - pcl[lab];
        float nll13   = lse - pcl[13];
        cls = (double)nll_lab - 0.05 * (double)nll13;
    }

    #pragma unroll
    for (int o = 16; o; o >>= 1) {
        l1sum += __shfl_down_sync(0xffffffffu, l1sum, o);
        gsum  += __shfl_down_sync(0xffffffffu, gsum, o);
        cls   += __shfl_down_sync(0xffffffffu, cls, o);
    }
    if (lane == 0) { redd[wid][0] = l1sum; redd[wid][1] = gsum; redd[wid][2] = cls; }
    __syncthreads();
    if (tid == 0) {
        double a = 0, g = 0, c = 0;
        #pragma unroll
        for (int k = 0; k < 4; k++) { a += redd[k][0]; g += redd[k][1]; c += redd[k][2]; }
        double base = g_basepart[b*4+0] + g_basepart[b*4+1] +
                      g_basepart[b*4+2] + g_basepart[b*4+3];
        double clsum = 0.05 * base + c;
        double wsum  = 128.0 + 772.0 * 0.05;
        double l1mean = a / (double)(TT * 4);
        double bbox = 5.0 * l1mean + 2.0 * (1.0 - g / (double)TT);
        g_partial[b] = (float)(bbox + clsum / wsum);
        __threadfence();
        unsigned old = atomicAdd(&g_count, 1u);
        s_last = (old == BB - 1) ? 1 : 0;
    }
    __syncthreads();

    if (s_last) {
        __threadfence();   // acquire: all g_partial visible
        double s = (tid < BB) ? (double)g_partial[tid] : 0.0;
        #pragma unroll
        for (int o = 16; o; o >>= 1) s += __shfl_down_sync(0xffffffffu, s, o);
        if (tid < 64 && lane == 0) sw[wid] = s;
        __syncthreads();
        if (tid == 0) {
            outp[0] = (float)((sw[0] + sw[1]) / (double)(BB * TT));
            g_count = 0;   // reset for next graph replay
        }
    }
}

// ---------------------------------------------------------------------------
extern "C" void kernel_launch(void* const* d_in, const int* in_sizes, int n_in,
                              void* d_out, int out_size)
{
    const float* pc = (const float*)d_in[0];  // predicted_class [B,Q,14]
    const float* pb = (const float*)d_in[1];  // predicted_bbox  [B,Q,4]
    const int*   tl = (const int*)d_in[2];    // target_labels   [B,T]
    const float* tb = (const float*)d_in[3];  // target_boxes    [B,T,4]

    softmax_kernel<<<dim3(4, BB), 256>>>(pc);
    rowmin_kernel<<<dim3(16, BB), 256>>>(pb, tl, tb);
    hungarian_kernel<<<BB, 256>>>(pc, pb, tl, tb, (float*)d_out);
}

// round 13
// speedup vs baseline: 1.9860x; 1.4848x over previous
#include <cuda_runtime.h>
#include <math.h>
#include <float.h>

#define BB 64
#define QQ 900
#define TT 128
#define C1 14    // NUM_CLASSES+1
#define QP 912   // padded Q stride for the transposed prob table (16B aligned)
#define NC 4     // columns owned per thread in the Dijkstra loop

// Scratch (static device globals; no allocation)
__device__ __align__(16) float g_probT[(size_t)BB*C1*QP];  // -softmax, [b][c][q]
__device__ float  g_lse[BB*QQ];
__device__ double g_basepart[BB*4];          // per-softmax-block sum of nll13
__device__ float  g_u[BB*TT];                // row minima
__device__ int    g_amin[BB*TT];             // row argmin (0-based col)
__device__ float  g_partial[BB];
__device__ unsigned g_count = 0;

// ---------------------------------------------------------------------------
// Kernel 0: softmax -> transposed negative-prob table + logsumexp + nll13 sum
// grid (4, B) x 256
// ---------------------------------------------------------------------------
__global__ void __launch_bounds__(256) softmax_kernel(const float* __restrict__ pc)
{
    int b   = blockIdx.y;
    int tid = threadIdx.x;
    int q   = blockIdx.x * 256 + tid;
    int lane = tid & 31, wid = tid >> 5;

    double base = 0.0;
    if (q < QQ) {
        const float* lg = pc + ((size_t)b * QQ + q) * C1;
        float l[C1];
        float m = -FLT_MAX;
        #pragma unroll
        for (int c = 0; c < C1; c++) { l[c] = lg[c]; m = fmaxf(m, l[c]); }
        float logit13 = l[13];
        float s = 0.f;
        #pragma unroll
        for (int c = 0; c < C1; c++) { l[c] = expf(l[c] - m); s += l[c]; }
        float inv = -1.0f / s;                       // negative probs
        float* dst = g_probT + (size_t)b * C1 * QP + q;
        #pragma unroll
        for (int c = 0; c < C1; c++) dst[(size_t)c * QP] = l[c] * inv;
        float lse = m + logf(s);
        g_lse[b * QQ + q] = lse;
        base = (double)(lse - logit13);              // nll at class 13
    }

    __shared__ double red[8];
    #pragma unroll
    for (int o = 16; o; o >>= 1) base += __shfl_down_sync(0xffffffffu, base, o);
    if (lane == 0) red[wid] = base;
    __syncthreads();
    if (tid == 0) {
        double s = 0.0;
        #pragma unroll
        for (int k = 0; k < 8; k++) s += red[k];
        g_basepart[b * 4 + blockIdx.x] = s;
    }
}

// ---------------------------------------------------------------------------
// on-the-fly cost of (target t, query j):  L1(boxes) + (-prob[label_t][j])
// Must be byte-identical in rowmin_kernel and hungarian_kernel.
// ---------------------------------------------------------------------------
__device__ __forceinline__ float cost_el(float4 pq, float4 t4, float cc)
{
    return (fabsf(pq.x - t4.x) + fabsf(pq.y - t4.y)) +
           (fabsf(pq.z - t4.z) + fabsf(pq.w - t4.w)) + cc;
}

// ---------------------------------------------------------------------------
// Kernel 1: row minima with on-the-fly costs. One warp per (b,t) row.
// grid (16, B) x 256
// ---------------------------------------------------------------------------
__global__ void __launch_bounds__(256) rowmin_kernel(
    const float* __restrict__ pb, const int* __restrict__ tl,
    const float* __restrict__ tb)
{
    int b    = blockIdx.y;
    int lane = threadIdx.x & 31;
    int t    = blockIdx.x * 8 + (threadIdx.x >> 5);

    const float4 t4 = ((const float4*)tb)[b * TT + t];
    const float* prow = g_probT + ((size_t)b * C1 + tl[b * TT + t]) * QP;
    const float4* pbB = (const float4*)pb + (size_t)b * QQ;

    float bv = FLT_MAX;
    int   bj = 0x7fffffff;
    for (int j = lane; j < QQ; j += 32) {
        float c = cost_el(pbB[j], t4, prow[j]);
        if (c < bv) { bv = c; bj = j; }      // strided scan keeps lowest j per lane
    }
    #pragma unroll
    for (int o = 16; o; o >>= 1) {
        float ov = __shfl_down_sync(0xffffffffu, bv, o);
        int   oj = __shfl_down_sync(0xffffffffu, bj, o);
        if (ov < bv || (ov == bv && oj < bj)) { bv = ov; bj = oj; }
    }
    if (lane == 0) {
        g_u[b * TT + t]    = bv;
        g_amin[b * TT + t] = bj;
    }
}

// ---------------------------------------------------------------------------
// Kernel 2: greedy matching + Dijkstra augments with REGISTER-resident
// per-column state (spc/v/used/box) + fused losses + last-block finalize.
// Thread tid owns columns j = tid+1+256k, k<4.  One 256-thread block/batch.
// ---------------------------------------------------------------------------
__global__ void __launch_bounds__(256) hungarian_kernel(
    const float* __restrict__ pc, const float* __restrict__ pb,
    const int* __restrict__ tl, const float* __restrict__ tb,
    float* __restrict__ outp)
{
    int b = blockIdx.x;
    int tid = threadIdx.x;
    int lane = tid & 31, wid = tid >> 5;

    __shared__ float  u[TT + 1];
    __shared__ short  p[QQ + 1];        // p[j] = row assigned to col j (1-based)
    __shared__ short  way[QQ + 1];
    __shared__ int    claim[QQ + 1];
    __shared__ short  freerows[TT];
    __shared__ short  predq[TT];
    __shared__ float4 spb[QQ];          // predicted boxes (for loss + reload)
    __shared__ float4 stb[TT];          // target boxes
    __shared__ int    slab[TT];         // target labels
    __shared__ int    s_nfree, s_j1, s_i0, s_done, s_last;
    __shared__ float  s_minval, s_ui0;
    __shared__ float  red_v[8];
    __shared__ int    red_j[8];
    __shared__ double redd[8][3];
    __shared__ double sw[2];

    const float* probB = g_probT + (size_t)b * C1 * QP;

    for (int j = tid; j <= QQ; j += 256) { p[j] = 0; claim[j] = 0x7fffffff; }
    for (int k = tid; k < QQ; k += 256) spb[k] = ((const float4*)pb)[b * QQ + k];
    if (tid < TT) {
        stb[tid]  = ((const float4*)tb)[b * TT + tid];
        slab[tid] = tl[b * TT + tid];
        u[tid + 1] = g_u[b * TT + tid];
    }
    if (tid == 0) s_nfree = 0;
    __syncthreads();

    // ---- per-thread owned-column registers ----
    int    jc[NC];
    bool   valid[NC];
    float4 boxreg[NC];
    float  vreg[NC];
    float  spcreg[NC];
    bool   usedreg[NC];
    #pragma unroll
    for (int k = 0; k < NC; k++) {
        jc[k] = tid + 1 + 256 * k;
        valid[k] = (jc[k] <= QQ);
        vreg[k] = 0.0f;
        if (valid[k]) boxreg[k] = spb[jc[k] - 1];
    }

    // ---- greedy matching on tight argmin edges (winner = lowest row) ----
    int myamin = -1;
    if (tid < TT) {
        myamin = g_amin[b * TT + tid];
        atomicMin(&claim[myamin + 1], tid);
    }
    __syncthreads();
    if (tid < TT) {
        int j = myamin + 1;
        if (claim[j] == tid) p[j] = (short)(tid + 1);
        else {
            int k = atomicAdd(&s_nfree, 1);
            freerows[k] = (short)(tid + 1);
        }
    }
    __syncthreads();
    int nfree = s_nfree;

    // ---- Dijkstra augment for each free row ----
    for (int fi = 0; fi < nfree; fi++) {
        int i = freerows[fi];
        #pragma unroll
        for (int k = 0; k < NC; k++) { spcreg[k] = FLT_MAX; usedreg[k] = false; }
        if (tid == 0) {
            p[0] = (short)i;
            s_minval = 0.0f;
            s_ui0 = u[i];
            s_i0 = i;
            s_j1 = 0;          // virtual root column
            s_done = 0;
        }
        __syncthreads();

        while (1) {
            int   j1prev = s_j1;
            float base   = s_minval - s_ui0;
            int   i0     = s_i0;
            float4 t4 = stb[i0 - 1];
            const float* prow = probB + (size_t)slab[i0 - 1] * QP;

            // mark the newly committed column (its owner flips its reg flag)
            #pragma unroll
            for (int k = 0; k < NC; k++)
                if (valid[k] && jc[k] == j1prev) usedreg[k] = true;

            // prefetch scattered prob entries for live columns
            float cc[NC];
            #pragma unroll
            for (int k = 0; k < NC; k++)
                if (valid[k] && !usedreg[k]) cc[k] = prow[jc[k] - 1];

            float bv = FLT_MAX;
            int   bj = 0x7fffffff;
            #pragma unroll
            for (int k = 0; k < NC; k++) {
                if (valid[k] && !usedreg[k]) {
                    float cst = cost_el(boxreg[k], t4, cc[k]);
                    float r = base + cst - vreg[k];
                    if (r < spcreg[k]) { spcreg[k] = r; way[jc[k]] = (short)j1prev; }
                    if (spcreg[k] < bv) { bv = spcreg[k]; bj = jc[k]; }  // ks ascend in j
                }
            }
            #pragma unroll
            for (int o = 16; o; o >>= 1) {
                float ov = __shfl_down_sync(0xffffffffu, bv, o);
                int   oj = __shfl_down_sync(0xffffffffu, bj, o);
                if (ov < bv || (ov == bv && oj < bj)) { bv = ov; bj = oj; }
            }
            if (lane == 0) { red_v[wid] = bv; red_j[wid] = bj; }
            __syncthreads();
            if (wid == 0) {
                bv = (lane < 8) ? red_v[lane] : FLT_MAX;
                bj = (lane < 8) ? red_j[lane] : 0x7fffffff;
                #pragma unroll
                for (int o = 4; o; o >>= 1) {
                    float ov = __shfl_down_sync(0xffffffffu, bv, o);
                    int   oj = __shfl_down_sync(0xffffffffu, bj, o);
                    if (ov < bv || (ov == bv && oj < bj)) { bv = ov; bj = oj; }
                }
                if (lane == 0) {
                    int r = p[bj];
                    s_minval = bv;
                    s_j1 = bj;
                    if (r == 0) s_done = 1;
                    else { s_i0 = r; s_ui0 = u[r]; }
                }
            }
            __syncthreads();
            if (s_done) break;
        }

        float minF = s_minval;
        int sink = s_j1;

        // owner-side dual update over tree columns (distinct rows per column)
        #pragma unroll
        for (int k = 0; k < NC; k++) {
            if (valid[k] && usedreg[k]) {
                float d = minF - spcreg[k];
                u[p[jc[k]]] += d;
                vreg[k] -= d;
            }
        }
        if (tid == 0) u[i] += minF;     // virtual root column 0: p[0]=i, spc=0
        __syncthreads();

        // augment along alternating path
        if (tid == 0) {
            int j0 = sink;
            while (j0) {
                int jn = way[j0];
                p[j0] = p[jn];
                j0 = jn;
            }
        }
        __syncthreads();
    }

    // emit assignment into shared
    for (int j = tid + 1; j <= QQ; j += 256) {
        int r = p[j];
        if (r > 0) predq[r - 1] = (short)(j - 1);
    }
    __syncthreads();

    // ---- fused per-batch losses ----
    double l1sum = 0.0, gsum = 0.0, cls = 0.0;
    if (tid < TT) {
        int t = tid;
        int q = predq[t];
        int lab = slab[t];
        float4 pq = spb[q];
        float4 t4 = stb[t];
        float px = pq.x, py = pq.y, pw = pq.z, ph = pq.w;
        float tx = t4.x, ty = t4.y, tw = t4.z, th = t4.w;

        l1sum = (double)(fabsf(px - tx) + fabsf(py - ty) +
                         fabsf(pw - tw) + fabsf(ph - th));

        float p1x = px - 0.5f * pw, p1y = py - 0.5f * ph;
        float p2x = px + 0.5f * pw, p2y = py + 0.5f * ph;
        float t1x = tx - 0.5f * tw, t1y = ty - 0.5f * th;
        float t2x = tx + 0.5f * tw, t2y = ty + 0.5f * th;
        float a1 = (p2x - p1x) * (p2y - p1y);
        float a2 = (t2x - t1x) * (t2y - t1y);
        float ltx = fmaxf(p1x, t1x), lty = fmaxf(p1y, t1y);
        float rbx = fminf(p2x, t2x), rby = fminf(p2y, t2y);
        float iw = fmaxf(rbx - ltx, 0.f), ih = fmaxf(rby - lty, 0.f);
        float inter = iw * ih;
        float uni = a1 + a2 - inter;
        float iou = inter / uni;
        float cx1 = fminf(p1x, t1x), cy1 = fminf(p1y, t1y);
        float cx2 = fmaxf(p2x, t2x), cy2 = fmaxf(p2y, t2y);
        float ac = (cx2 - cx1) * (cy2 - cy1);
        gsum = (double)(iou - (ac - uni) / ac);

        float lse = g_lse[b * QQ + q];
        const float* pcl = pc + ((size_t)b * QQ + q) * C1;
        float nll_lab = lse - pcl[lab];
        float nll13   = lse - pcl[13];
        cls = (double)nll_lab - 0.05 * (double)nll13;
    }

    #pragma unroll
    for (int o = 16; o; o >>= 1) {
        l1sum += __shfl_down_sync(0xffffffffu, l1sum, o);
        gsum  += __shfl_down_sync(0xffffffffu, gsum, o);
        cls   += __shfl_down_sync(0xffffffffu, cls, o);
    }
    if (lane == 0) { redd[wid][0] = l1sum; redd[wid][1] = gsum; redd[wid][2] = cls; }
    __syncthreads();
    if (tid == 0) {
        double a = 0, g = 0, c = 0;
        #pragma unroll
        for (int k = 0; k < 4; k++) { a += redd[k][0]; g += redd[k][1]; c += redd[k][2]; }
        double base = g_basepart[b*4+0] + g_basepart[b*4+1] +
                      g_basepart[b*4+2] + g_basepart[b*4+3];
        double clsum = 0.05 * base + c;
        double wsum  = 128.0 + 772.0 * 0.05;
        double l1mean = a / (double)(TT * 4);
        double bbox = 5.0 * l1mean + 2.0 * (1.0 - g / (double)TT);
        g_partial[b] = (float)(bbox + clsum / wsum);
        __threadfence();
        unsigned old = atomicAdd(&g_count, 1u);
        s_last = (old == BB - 1) ? 1 : 0;
    }
    __syncthreads();

    if (s_last) {
        __threadfence();   // acquire: all g_partial visible
        double s = (tid < BB) ? (double)g_partial[tid] : 0.0;
        #pragma unroll
        for (int o = 16; o; o >>= 1) s += __shfl_down_sync(0xffffffffu, s, o);
        if (tid < 64 && lane == 0) sw[wid] = s;
        __syncthreads();
        if (tid == 0) {
            outp[0] = (float)((sw[0] + sw[1]) / (double)(BB * TT));
            g_count = 0;   // reset for next graph replay
        }
    }
}

// ---------------------------------------------------------------------------
extern "C" void kernel_launch(void* const* d_in, const int* in_sizes, int n_in,
                              void* d_out, int out_size)
{
    const float* pc = (const float*)d_in[0];  // predicted_class [B,Q,14]
    const float* pb = (const float*)d_in[1];  // predicted_bbox  [B,Q,4]
    const int*   tl = (const int*)d_in[2];    // target_labels   [B,T]
    const float* tb = (const float*)d_in[3];  // target_boxes    [B,T,4]

    softmax_kernel<<<dim3(4, BB), 256>>>(pc);
    rowmin_kernel<<<dim3(16, BB), 256>>>(pb, tl, tb);
    hungarian_kernel<<<BB, 256>>>(pc, pb, tl, tb, (float*)d_out);
}